// round 12
// baseline (speedup 1.0000x reference)
#include <cuda_runtime.h>
#include <math.h>

// ----------------------------------------------------------------------------
// Software rasterizer matching the JAX reference.
// winner(pixel) = lexicographic argmax over covering triangles of (z, index),
// zbuf init = min vertex z. Deferred shading (one bilinear sample per pixel).
// Triangles bucket-sorted by zmax desc; per-slot term key = bucket upper edge
// (+1 bucket pad) -> non-increasing, >= all remaining zmax. Termination is
// checked at chunk/quantum granularity only (scanning extra triangles is safe:
// the winner is an argmax with exact compares over a superset).
// Render: 32x8 tile, 1 pixel/thread; chunks compacted against the tile at load
// time (global->reg->test->smem); survivor loop is branch-light for ILP.
// ----------------------------------------------------------------------------

#define MAXK  2048
#define CHUNK 256
#define NBUK  256

__device__ float4 g_tri[MAXK * 4];   // bucket-ordered triangle structs
__device__ int    g_ntri;            // number of active slots
__device__ float  g_zinit;           // min vertex z

__device__ __forceinline__ float blk_reduce(float v, bool do_min, float* s_red, int tid) {
    for (int o = 16; o > 0; o >>= 1) {
        float u = __shfl_xor_sync(0xffffffffu, v, o);
        v = do_min ? fminf(v, u) : fmaxf(v, u);
    }
    if ((tid & 31) == 0) s_red[tid >> 5] = v;
    __syncthreads();
    if (tid < 32) {
        float u = s_red[tid];
        for (int o = 16; o > 0; o >>= 1) {
            float w = __shfl_xor_sync(0xffffffffu, u, o);
            u = do_min ? fminf(u, w) : fmaxf(u, w);
        }
        if (tid == 0) s_red[0] = u;
    }
    __syncthreads();
    float r = s_red[0];
    __syncthreads();
    return r;
}

// ---- fused setup: zinit + zmax + bucket sort + struct build ----------------
__global__ void __launch_bounds__(1024) setup_kernel(
    const float* __restrict__ vertices, const int* __restrict__ faces,
    int V, int K)
{
    __shared__ float s_zmax[MAXK];
    __shared__ int   s_pos[MAXK];
    __shared__ int   s_hist[NBUK];
    __shared__ int   s_cnt[NBUK];
    __shared__ float s_red[32];
    __shared__ int   sh_n;
    int tid = threadIdx.x;

    // 1. zinit = min vertex z
    float m = INFINITY;
    for (int v = tid; v < V; v += 1024) m = fminf(m, vertices[v * 3 + 2]);
    m = blk_reduce(m, true, s_red, tid);
    if (tid == 0) g_zinit = m;

    // 2. per-triangle zmax (-inf if culled)
    float mymax = -INFINITY, mymin = INFINITY;
    for (int t = tid; t < K; t += 1024) {
        int i0 = faces[3*t], i1 = faces[3*t+1], i2 = faces[3*t+2];
        float v0x = vertices[i0*3+0], v0y = vertices[i0*3+1], v0z = vertices[i0*3+2];
        float v1x = vertices[i1*3+0], v1y = vertices[i1*3+1], v1z = vertices[i1*3+2];
        float v2x = vertices[i2*3+0], v2y = vertices[i2*3+1], v2z = vertices[i2*3+2];
        float w = (v1x - v0x) * (v2y - v0y) - (v1y - v0y) * (v2x - v0x);
        float zm = -INFINITY;
        if (w >= 1e-9f) {
            zm = fmaxf(v0z, fmaxf(v1z, v2z));
            mymax = fmaxf(mymax, zm);
            mymin = fminf(mymin, zm);
        }
        s_zmax[t] = zm;
    }
    float zh = blk_reduce(mymax, false, s_red, tid);
    float zl = blk_reduce(mymin, true,  s_red, tid);
    float wd = fmaxf((zh - zl) / (float)NBUK, 1e-30f);

    // 3. histogram (bucket 0 = highest zmax)
    if (tid < NBUK) s_hist[tid] = 0;
    __syncthreads();
    for (int t = tid; t < K; t += 1024) {
        float zm = s_zmax[t];
        if (zm != -INFINITY) {
            int b = (int)((zh - zm) / wd);
            b = min(max(b, 0), NBUK - 1);
            atomicAdd(&s_hist[b], 1);
        }
    }
    __syncthreads();

    // 4. exclusive scan (single warp: 8 buckets per lane + shfl scan)
    if (tid < 32) {
        int base2 = tid * 8;
        int v[8]; int s = 0;
        #pragma unroll
        for (int q = 0; q < 8; ++q) { v[q] = s_hist[base2 + q]; s += v[q]; }
        int incl = s;
        for (int o = 1; o < 32; o <<= 1) {
            int u = __shfl_up_sync(0xffffffffu, incl, o);
            if (tid >= o) incl += u;
        }
        int run = incl - s;
        #pragma unroll
        for (int q = 0; q < 8; ++q) { s_cnt[base2 + q] = run; run += v[q]; }
        if (tid == 31) sh_n = run;
    }
    __syncthreads();

    // 5. scatter slot assignment
    for (int t = tid; t < K; t += 1024) {
        float zm = s_zmax[t];
        int pos = -1;
        if (zm != -INFINITY) {
            int b = (int)((zh - zm) / wd);
            b = min(max(b, 0), NBUK - 1);
            pos = atomicAdd(&s_cnt[b], 1);
        }
        s_pos[t] = pos;
    }
    if (tid == 0) g_ntri = sh_n;
    __syncthreads();

    // 6. build structs. term key = bucket upper edge + one-bucket pad:
    //    term(b) = zh - (b-1)*wd >= zmax of everything in buckets >= b,
    //    margin ~wd >> f32 rounding; non-increasing across slots.
    // Layout per slot (4 x float4):
    //  [0] A0 B0 C0 term   (edge pAB: A*px + B*py + C)
    //  [1] A1 B1 C1 z0     (edge pCB -> w1)
    //  [2] A2 B2 C2 z1     (edge pCA -> w2)
    //  [3] w   z2  idx  0
    for (int t = tid; t < K; t += 1024) {
        int pos = s_pos[t];
        if (pos < 0) continue;
        float zm = s_zmax[t];
        int b = (int)((zh - zm) / wd);
        b = min(max(b, 0), NBUK - 1);
        float term = zh - (float)(b - 1) * wd;

        int i0 = faces[t*3+0], i1 = faces[t*3+1], i2 = faces[t*3+2];
        float v0x = vertices[i0*3+0], v0y = vertices[i0*3+1], v0z = vertices[i0*3+2];
        float v1x = vertices[i1*3+0], v1y = vertices[i1*3+1], v1z = vertices[i1*3+2];
        float v2x = vertices[i2*3+0], v2y = vertices[i2*3+1], v2z = vertices[i2*3+2];
        float w = (v1x - v0x) * (v2y - v0y) - (v1y - v0y) * (v2x - v0x);

        float a0 = v0y - v1y, b0 = v0x - v1x;
        float C0 = (float)((double)v1y * (double)b0 - (double)v1x * (double)a0);
        float a1 = v1y - v2y, b1 = v1x - v2x;
        float C1 = (float)((double)v2y * (double)b1 - (double)v2x * (double)a1);
        float a2 = v2y - v0y, b2 = v2x - v0x;
        float C2 = (float)((double)v0y * (double)b2 - (double)v0x * (double)a2);

        g_tri[pos*4+0] = make_float4(a0, -b0, C0, term);
        g_tri[pos*4+1] = make_float4(a1, -b1, C1, v0z);
        g_tri[pos*4+2] = make_float4(a2, -b2, C2, v1z);
        g_tri[pos*4+3] = make_float4(w, v2z, __int_as_float(t), 0.0f);
    }
}

// ---- main render: 32x8 tile, 1 pixel/thread --------------------------------
__global__ void __launch_bounds__(256) render_kernel(
    const int* __restrict__ uvfaces, const float* __restrict__ uv,
    const float* __restrict__ uvmap, float* __restrict__ out,
    int S, int T)
{
    __shared__ float4 s_ktri[CHUNK * 4];   // compacted survivors (dense)
    __shared__ int    s_wcnt[8];
    __shared__ int    s_woff[8];
    __shared__ int    s_lcnt;
    __shared__ float  s_head;              // chunk-head term key

    int n = g_ntri;

    int j = blockIdx.x * 32 + threadIdx.x;
    int i = blockIdx.y * 8 + threadIdx.y;
    int tid = threadIdx.y * 32 + threadIdx.x;
    int warp = tid >> 5, lane = tid & 31;
    bool inrange = (j < S) && (i < S);
    int jc = min(j, S - 1), ic = min(i, S - 1);

    // pts[i][j] = (lin[j], lin[S-1-i]), lin = linspace(-1, 1, S)
    float step = 2.0f / (float)(S - 1);
    float px = fmaf((float)jc, step, -1.0f);
    float py = fmaf((float)(S - 1 - ic), step, -1.0f);

    // tile bounds in (px, py) space
    int j0 = min(blockIdx.x * 32,      S - 1), j1 = min(blockIdx.x * 32 + 31, S - 1);
    int i0 = min(blockIdx.y * 8,       S - 1), i1 = min(blockIdx.y * 8 + 7,   S - 1);
    float xl = fmaf((float)j0, step, -1.0f), xh = fmaf((float)j1, step, -1.0f);
    float yl = fmaf((float)(S - 1 - i1), step, -1.0f);
    float yh = fmaf((float)(S - 1 - i0), step, -1.0f);

    float bestz = g_zinit;
    int   bestk = -1;
    float bw1 = 0.f, bw2 = 0.f;
    bool done = false;

    for (int base = 0; base < n; base += CHUNK) {
        int cnt = min(CHUNK, n - base);
        __syncthreads();   // protect s_ktri reuse across iterations

        // --- compact-on-load: global -> registers -> tile test -> smem ---
        bool keep = false;
        float4 r0v, r1v, r2v;
        if (tid < cnt) {
            const float4* gp = &g_tri[(base + tid) * 4];
            r0v = gp[0]; r1v = gp[1]; r2v = gp[2];
            if (tid == 0) s_head = r0v.w;
            float m0 = fmaxf(r0v.x*xl, r0v.x*xh) + fmaxf(r0v.y*yl, r0v.y*yh) + r0v.z;
            float m1 = fmaxf(r1v.x*xl, r1v.x*xh) + fmaxf(r1v.y*yl, r1v.y*yh) + r1v.z;
            float m2 = fmaxf(r2v.x*xl, r2v.x*xh) + fmaxf(r2v.y*yl, r2v.y*yh) + r2v.z;
            keep = (fminf(m0, fminf(m1, m2)) > -1e-3f);  // margin >> f32 slack
        }
        unsigned ball = __ballot_sync(0xffffffffu, keep);
        int pre = __popc(ball & ((1u << lane) - 1u));
        if (lane == 0) s_wcnt[warp] = __popc(ball);
        __syncthreads();
        if (tid == 0) {
            int s = 0;
            #pragma unroll
            for (int w = 0; w < 8; ++w) { s_woff[w] = s; s += s_wcnt[w]; }
            s_lcnt = s;
        }
        __syncthreads();
        if (keep) {
            float4 r3v = g_tri[(base + tid) * 4 + 3];
            int pos = s_woff[warp] + pre;
            s_ktri[pos*4+0] = r0v;
            s_ktri[pos*4+1] = r1v;
            s_ktri[pos*4+2] = r2v;
            s_ktri[pos*4+3] = r3v;
        }
        __syncthreads();
        int lcnt = s_lcnt;

        if (!done) {
            if (s_head < bestz) {
                done = true;   // chunk-head term can't beat bestz -> nothing later can
            } else {
                // Branch-light survivor scan. Termination checked only every
                // 32 survivors: scanning extras is SAFE (argmax over superset,
                // exact compares; reference scans everything anyway).
                for (int q0 = 0; q0 < lcnt; q0 += 32) {
                    if (s_ktri[q0*4].w < bestz) { done = true; break; }
                    int qe = min(q0 + 32, lcnt);
                    #pragma unroll 2
                    for (int mI = q0; mI < qe; ++mI) {
                        float4 a = s_ktri[mI*4+0];
                        float4 b = s_ktri[mI*4+1];
                        float4 c = s_ktri[mI*4+2];
                        float e0 = fmaf(a.x, px, fmaf(a.y, py, a.z));
                        float e1 = fmaf(b.x, px, fmaf(b.y, py, b.z));
                        float e2 = fmaf(c.x, px, fmaf(c.y, py, c.z));
                        if (fminf(e0, fminf(e1, e2)) > 0.f) {
                            float4 d = s_ktri[mI*4+3];
                            float w1 = e1 / d.x;          // pCB / w (exact like ref)
                            float w2 = e2 / d.x;          // pCA / w
                            float w3 = 1.0f - w1 - w2;
                            float z = w1 * b.w + w2 * c.w + w3 * d.y;
                            int k = __float_as_int(d.z);
                            if (z > bestz || (z == bestz && k > bestk)) {
                                bestz = z; bestk = k; bw1 = w1; bw2 = w2;
                            }
                        }
                    }
                }
            }
        }
        if (__syncthreads_and((int)done)) break;
    }

    if (!inrange) return;
    int SS = S * S;
    int p = i * S + j;

    if (bestk >= 0) {
        int f0 = uvfaces[bestk*3+0], f1 = uvfaces[bestk*3+1], f2i = uvfaces[bestk*3+2];
        float u0x = uv[f0*2+0]  * 2.0f - 1.0f, u0y = uv[f0*2+1]  * 2.0f - 1.0f;
        float u1x = uv[f1*2+0]  * 2.0f - 1.0f, u1y = uv[f1*2+1]  * 2.0f - 1.0f;
        float u2x = uv[f2i*2+0] * 2.0f - 1.0f, u2y = uv[f2i*2+1] * 2.0f - 1.0f;
        float w3 = 1.0f - bw1 - bw2;
        float x = bw1 * u0x + bw2 * u1x + w3 * u2x;
        float y = bw1 * u0y + bw2 * u1y + w3 * u2y;

        float ix = (x + 1.0f) * (float)(T - 1) * 0.5f;
        float iy = (y + 1.0f) * (float)(T - 1) * 0.5f;
        float ix0f = floorf(ix), iy0f = floorf(iy);
        float wx1 = ix - ix0f, wx0 = 1.0f - wx1;
        float wy1 = iy - iy0f, wy0 = 1.0f - wy1;
        int ix0 = (int)ix0f, iy0 = (int)iy0f;
        int ix1 = ix0 + 1,   iy1 = iy0 + 1;

        float m00 = (ix0 >= 0 && ix0 <= T-1 && iy0 >= 0 && iy0 <= T-1) ? 1.f : 0.f;
        float m01 = (ix1 >= 0 && ix1 <= T-1 && iy0 >= 0 && iy0 <= T-1) ? 1.f : 0.f;
        float m10 = (ix0 >= 0 && ix0 <= T-1 && iy1 >= 0 && iy1 <= T-1) ? 1.f : 0.f;
        float m11 = (ix1 >= 0 && ix1 <= T-1 && iy1 >= 0 && iy1 <= T-1) ? 1.f : 0.f;
        int cx0 = min(max(ix0, 0), T-1), cx1 = min(max(ix1, 0), T-1);
        int cy0 = min(max(iy0, 0), T-1), cy1 = min(max(iy1, 0), T-1);
        float k00 = (wy0 * wx0) * m00, k01 = (wy0 * wx1) * m01;
        float k10 = (wy1 * wx0) * m10, k11 = (wy1 * wx1) * m11;

        #pragma unroll
        for (int ch = 0; ch < 3; ++ch) {
            const float* img = uvmap + ch * T * T;
            float v = img[cy0*T + cx0] * k00 + img[cy0*T + cx1] * k01
                    + img[cy1*T + cx0] * k10 + img[cy1*T + cx1] * k11;
            out[ch*SS + p] = v;
        }
        out[3*SS + p] = 1.0f;
    } else {
        out[0*SS + p] = 0.f; out[1*SS + p] = 0.f;
        out[2*SS + p] = 0.f; out[3*SS + p] = 0.f;
    }
}

// ---- launch ----------------------------------------------------------------
extern "C" void kernel_launch(void* const* d_in, const int* in_sizes, int n_in,
                              void* d_out, int out_size) {
    const float* vertices = (const float*)d_in[0];
    const int*   faces    = (const int*)d_in[1];
    const float* uv       = (const float*)d_in[2];
    const int*   uvfaces  = (const int*)d_in[3];
    const float* uvmap    = (const float*)d_in[4];

    int V = in_sizes[0] / 3;
    int K = in_sizes[1] / 3;
    int T = (int)(sqrt((double)(in_sizes[4] / 3)) + 0.5);
    int S = (int)(sqrt((double)(out_size / 4)) + 0.5);
    if (K > MAXK) K = MAXK;

    setup_kernel<<<1, 1024>>>(vertices, faces, V, K);

    dim3 blk(32, 8);
    dim3 grd((S + 31) / 32, (S + 7) / 8);
    render_kernel<<<grd, blk>>>(uvfaces, uv, uvmap, (float*)d_out, S, T);
}

// round 14
// speedup vs baseline: 1.1100x; 1.1100x over previous
#include <cuda_runtime.h>
#include <math.h>

// ----------------------------------------------------------------------------
// Software rasterizer matching the JAX reference.
// winner(pixel) = lexicographic argmax over covering triangles of (z, index),
// zbuf init = min vertex z. Deferred shading (one bilinear sample per pixel).
// Triangles bucket-sorted by zmax desc; per-slot term key = bucket upper edge
// (+1 bucket pad) -> non-increasing and >= all remaining zmax + ulp slack.
// Render (R7 config): 32x8 tile, 1 pixel/thread, per-survivor termination;
// chunks compacted against the tile at load time (global->reg->test->smem).
// Setup (R11 config): single-warp shfl scan for the bucket prefix sum.
// ----------------------------------------------------------------------------

#define MAXK  2048
#define CHUNK 256
#define NBUK  256

__device__ float4 g_tri[MAXK * 4];   // bucket-ordered triangle structs
__device__ int    g_ntri;            // number of active slots
__device__ float  g_zinit;           // min vertex z

__device__ __forceinline__ float blk_reduce(float v, bool do_min, float* s_red, int tid) {
    for (int o = 16; o > 0; o >>= 1) {
        float u = __shfl_xor_sync(0xffffffffu, v, o);
        v = do_min ? fminf(v, u) : fmaxf(v, u);
    }
    if ((tid & 31) == 0) s_red[tid >> 5] = v;
    __syncthreads();
    if (tid < 32) {
        float u = s_red[tid];
        for (int o = 16; o > 0; o >>= 1) {
            float w = __shfl_xor_sync(0xffffffffu, u, o);
            u = do_min ? fminf(u, w) : fmaxf(u, w);
        }
        if (tid == 0) s_red[0] = u;
    }
    __syncthreads();
    float r = s_red[0];
    __syncthreads();
    return r;
}

// ---- fused setup: zinit + zmax + bucket sort + struct build ----------------
__global__ void __launch_bounds__(1024) setup_kernel(
    const float* __restrict__ vertices, const int* __restrict__ faces,
    int V, int K)
{
    __shared__ float s_zmax[MAXK];
    __shared__ int   s_pos[MAXK];
    __shared__ int   s_hist[NBUK];
    __shared__ int   s_cnt[NBUK];
    __shared__ float s_red[32];
    __shared__ int   sh_n;
    int tid = threadIdx.x;

    // 1. zinit = min vertex z
    float m = INFINITY;
    for (int v = tid; v < V; v += 1024) m = fminf(m, vertices[v * 3 + 2]);
    m = blk_reduce(m, true, s_red, tid);
    if (tid == 0) g_zinit = m;

    // 2. per-triangle zmax (-inf if culled)
    float mymax = -INFINITY, mymin = INFINITY;
    for (int t = tid; t < K; t += 1024) {
        int i0 = faces[3*t], i1 = faces[3*t+1], i2 = faces[3*t+2];
        float v0x = vertices[i0*3+0], v0y = vertices[i0*3+1], v0z = vertices[i0*3+2];
        float v1x = vertices[i1*3+0], v1y = vertices[i1*3+1], v1z = vertices[i1*3+2];
        float v2x = vertices[i2*3+0], v2y = vertices[i2*3+1], v2z = vertices[i2*3+2];
        float w = (v1x - v0x) * (v2y - v0y) - (v1y - v0y) * (v2x - v0x);
        float zm = -INFINITY;
        if (w >= 1e-9f) {
            zm = fmaxf(v0z, fmaxf(v1z, v2z));
            mymax = fmaxf(mymax, zm);
            mymin = fminf(mymin, zm);
        }
        s_zmax[t] = zm;
    }
    float zh = blk_reduce(mymax, false, s_red, tid);
    float zl = blk_reduce(mymin, true,  s_red, tid);
    float wd = fmaxf((zh - zl) / (float)NBUK, 1e-30f);

    // 3. histogram (bucket 0 = highest zmax)
    if (tid < NBUK) s_hist[tid] = 0;
    __syncthreads();
    for (int t = tid; t < K; t += 1024) {
        float zm = s_zmax[t];
        if (zm != -INFINITY) {
            int b = (int)((zh - zm) / wd);
            b = min(max(b, 0), NBUK - 1);
            atomicAdd(&s_hist[b], 1);
        }
    }
    __syncthreads();

    // 4. exclusive scan (single warp: 8 buckets per lane + shfl scan)
    if (tid < 32) {
        int base2 = tid * 8;
        int v[8]; int s = 0;
        #pragma unroll
        for (int q = 0; q < 8; ++q) { v[q] = s_hist[base2 + q]; s += v[q]; }
        int incl = s;
        for (int o = 1; o < 32; o <<= 1) {
            int u = __shfl_up_sync(0xffffffffu, incl, o);
            if (tid >= o) incl += u;
        }
        int run = incl - s;
        #pragma unroll
        for (int q = 0; q < 8; ++q) { s_cnt[base2 + q] = run; run += v[q]; }
        if (tid == 31) sh_n = run;
    }
    __syncthreads();

    // 5. scatter slot assignment
    for (int t = tid; t < K; t += 1024) {
        float zm = s_zmax[t];
        int pos = -1;
        if (zm != -INFINITY) {
            int b = (int)((zh - zm) / wd);
            b = min(max(b, 0), NBUK - 1);
            pos = atomicAdd(&s_cnt[b], 1);
        }
        s_pos[t] = pos;
    }
    if (tid == 0) g_ntri = sh_n;
    __syncthreads();

    // 6. build structs. term key = bucket upper edge + one-bucket pad:
    //    term(b) = zh - (b-1)*wd >= zmax of everything in buckets >= b,
    //    margin ~wd >> f32 rounding; non-increasing across slots.
    // Layout per slot (4 x float4):
    //  [0] A0 B0 C0 term   (edge pAB: A*px + B*py + C)
    //  [1] A1 B1 C1 z0     (edge pCB -> w1)
    //  [2] A2 B2 C2 z1     (edge pCA -> w2)
    //  [3] w   z2  idx  0
    for (int t = tid; t < K; t += 1024) {
        int pos = s_pos[t];
        if (pos < 0) continue;
        float zm = s_zmax[t];
        int b = (int)((zh - zm) / wd);
        b = min(max(b, 0), NBUK - 1);
        float term = zh - (float)(b - 1) * wd;

        int i0 = faces[t*3+0], i1 = faces[t*3+1], i2 = faces[t*3+2];
        float v0x = vertices[i0*3+0], v0y = vertices[i0*3+1], v0z = vertices[i0*3+2];
        float v1x = vertices[i1*3+0], v1y = vertices[i1*3+1], v1z = vertices[i1*3+2];
        float v2x = vertices[i2*3+0], v2y = vertices[i2*3+1], v2z = vertices[i2*3+2];
        float w = (v1x - v0x) * (v2y - v0y) - (v1y - v0y) * (v2x - v0x);

        float a0 = v0y - v1y, b0 = v0x - v1x;
        float C0 = (float)((double)v1y * (double)b0 - (double)v1x * (double)a0);
        float a1 = v1y - v2y, b1 = v1x - v2x;
        float C1 = (float)((double)v2y * (double)b1 - (double)v2x * (double)a1);
        float a2 = v2y - v0y, b2 = v2x - v0x;
        float C2 = (float)((double)v0y * (double)b2 - (double)v0x * (double)a2);

        g_tri[pos*4+0] = make_float4(a0, -b0, C0, term);
        g_tri[pos*4+1] = make_float4(a1, -b1, C1, v0z);
        g_tri[pos*4+2] = make_float4(a2, -b2, C2, v1z);
        g_tri[pos*4+3] = make_float4(w, v2z, __int_as_float(t), 0.0f);
    }
}

// ---- main render: 32x8 tile, 1 pixel/thread (R7 config) --------------------
__global__ void __launch_bounds__(256) render_kernel(
    const int* __restrict__ uvfaces, const float* __restrict__ uv,
    const float* __restrict__ uvmap, float* __restrict__ out,
    int S, int T)
{
    __shared__ float4 s_ktri[CHUNK * 4];   // compacted survivors (dense)
    __shared__ int    s_wcnt[8];
    __shared__ int    s_woff[8];
    __shared__ int    s_lcnt;
    __shared__ float  s_head;              // chunk-head term key

    int n = g_ntri;

    int j = blockIdx.x * 32 + threadIdx.x;
    int i = blockIdx.y * 8 + threadIdx.y;
    int tid = threadIdx.y * 32 + threadIdx.x;
    int warp = tid >> 5, lane = tid & 31;
    bool inrange = (j < S) && (i < S);
    int jc = min(j, S - 1), ic = min(i, S - 1);

    // pts[i][j] = (lin[j], lin[S-1-i]), lin = linspace(-1, 1, S)
    float step = 2.0f / (float)(S - 1);
    float px = fmaf((float)jc, step, -1.0f);
    float py = fmaf((float)(S - 1 - ic), step, -1.0f);

    // tile bounds in (px, py) space
    int j0 = min(blockIdx.x * 32,      S - 1), j1 = min(blockIdx.x * 32 + 31, S - 1);
    int i0 = min(blockIdx.y * 8,       S - 1), i1 = min(blockIdx.y * 8 + 7,   S - 1);
    float xl = fmaf((float)j0, step, -1.0f), xh = fmaf((float)j1, step, -1.0f);
    float yl = fmaf((float)(S - 1 - i1), step, -1.0f);
    float yh = fmaf((float)(S - 1 - i0), step, -1.0f);

    float bestz = g_zinit;
    int   bestk = -1;
    float bw1 = 0.f, bw2 = 0.f;
    bool done = false;

    for (int base = 0; base < n; base += CHUNK) {
        int cnt = min(CHUNK, n - base);
        __syncthreads();   // protect s_ktri reuse across iterations

        // --- compact-on-load: global -> registers -> tile test -> smem ---
        bool keep = false;
        float4 r0v, r1v, r2v;
        if (tid < cnt) {
            const float4* gp = &g_tri[(base + tid) * 4];
            r0v = gp[0]; r1v = gp[1]; r2v = gp[2];
            if (tid == 0) s_head = r0v.w;
            float m0 = fmaxf(r0v.x*xl, r0v.x*xh) + fmaxf(r0v.y*yl, r0v.y*yh) + r0v.z;
            float m1 = fmaxf(r1v.x*xl, r1v.x*xh) + fmaxf(r1v.y*yl, r1v.y*yh) + r1v.z;
            float m2 = fmaxf(r2v.x*xl, r2v.x*xh) + fmaxf(r2v.y*yl, r2v.y*yh) + r2v.z;
            keep = (fminf(m0, fminf(m1, m2)) > -1e-3f);  // margin >> f32 slack
        }
        unsigned ball = __ballot_sync(0xffffffffu, keep);
        int pre = __popc(ball & ((1u << lane) - 1u));
        if (lane == 0) s_wcnt[warp] = __popc(ball);
        __syncthreads();
        if (tid == 0) {
            int s = 0;
            #pragma unroll
            for (int w = 0; w < 8; ++w) { s_woff[w] = s; s += s_wcnt[w]; }
            s_lcnt = s;
        }
        __syncthreads();
        if (keep) {
            float4 r3v = g_tri[(base + tid) * 4 + 3];
            int pos = s_woff[warp] + pre;
            s_ktri[pos*4+0] = r0v;
            s_ktri[pos*4+1] = r1v;
            s_ktri[pos*4+2] = r2v;
            s_ktri[pos*4+3] = r3v;
        }
        __syncthreads();
        int lcnt = s_lcnt;

        if (!done) {
            if (s_head < bestz) {
                done = true;   // chunk-head term can't beat bestz -> nothing later can
            } else {
                for (int mI = 0; mI < lcnt; ++mI) {
                    float4 a = s_ktri[mI*4+0];
                    if (a.w < bestz) { done = true; break; }  // term non-increasing
                    float e0 = fmaf(a.x, px, fmaf(a.y, py, a.z));
                    float4 b = s_ktri[mI*4+1];
                    float e1 = fmaf(b.x, px, fmaf(b.y, py, b.z));
                    float4 c = s_ktri[mI*4+2];
                    float e2 = fmaf(c.x, px, fmaf(c.y, py, c.z));
                    if (fminf(e0, fminf(e1, e2)) > 0.f) {
                        float4 d = s_ktri[mI*4+3];
                        float w1 = e1 / d.x;          // pCB / w (exact like ref)
                        float w2 = e2 / d.x;          // pCA / w
                        float w3 = 1.0f - w1 - w2;
                        float z = w1 * b.w + w2 * c.w + w3 * d.y;
                        int k = __float_as_int(d.z);
                        if (z > bestz || (z == bestz && k > bestk)) {
                            bestz = z; bestk = k; bw1 = w1; bw2 = w2;
                        }
                    }
                }
            }
        }
        if (__syncthreads_and((int)done)) break;
    }

    if (!inrange) return;
    int SS = S * S;
    int p = i * S + j;

    if (bestk >= 0) {
        int f0 = uvfaces[bestk*3+0], f1 = uvfaces[bestk*3+1], f2i = uvfaces[bestk*3+2];
        float u0x = uv[f0*2+0]  * 2.0f - 1.0f, u0y = uv[f0*2+1]  * 2.0f - 1.0f;
        float u1x = uv[f1*2+0]  * 2.0f - 1.0f, u1y = uv[f1*2+1]  * 2.0f - 1.0f;
        float u2x = uv[f2i*2+0] * 2.0f - 1.0f, u2y = uv[f2i*2+1] * 2.0f - 1.0f;
        float w3 = 1.0f - bw1 - bw2;
        float x = bw1 * u0x + bw2 * u1x + w3 * u2x;
        float y = bw1 * u0y + bw2 * u1y + w3 * u2y;

        float ix = (x + 1.0f) * (float)(T - 1) * 0.5f;
        float iy = (y + 1.0f) * (float)(T - 1) * 0.5f;
        float ix0f = floorf(ix), iy0f = floorf(iy);
        float wx1 = ix - ix0f, wx0 = 1.0f - wx1;
        float wy1 = iy - iy0f, wy0 = 1.0f - wy1;
        int ix0 = (int)ix0f, iy0 = (int)iy0f;
        int ix1 = ix0 + 1,   iy1 = iy0 + 1;

        float m00 = (ix0 >= 0 && ix0 <= T-1 && iy0 >= 0 && iy0 <= T-1) ? 1.f : 0.f;
        float m01 = (ix1 >= 0 && ix1 <= T-1 && iy0 >= 0 && iy0 <= T-1) ? 1.f : 0.f;
        float m10 = (ix0 >= 0 && ix0 <= T-1 && iy1 >= 0 && iy1 <= T-1) ? 1.f : 0.f;
        float m11 = (ix1 >= 0 && ix1 <= T-1 && iy1 >= 0 && iy1 <= T-1) ? 1.f : 0.f;
        int cx0 = min(max(ix0, 0), T-1), cx1 = min(max(ix1, 0), T-1);
        int cy0 = min(max(iy0, 0), T-1), cy1 = min(max(iy1, 0), T-1);
        float k00 = (wy0 * wx0) * m00, k01 = (wy0 * wx1) * m01;
        float k10 = (wy1 * wx0) * m10, k11 = (wy1 * wx1) * m11;

        #pragma unroll
        for (int ch = 0; ch < 3; ++ch) {
            const float* img = uvmap + ch * T * T;
            float v = img[cy0*T + cx0] * k00 + img[cy0*T + cx1] * k01
                    + img[cy1*T + cx0] * k10 + img[cy1*T + cx1] * k11;
            out[ch*SS + p] = v;
        }
        out[3*SS + p] = 1.0f;
    } else {
        out[0*SS + p] = 0.f; out[1*SS + p] = 0.f;
        out[2*SS + p] = 0.f; out[3*SS + p] = 0.f;
    }
}

// ---- launch ----------------------------------------------------------------
extern "C" void kernel_launch(void* const* d_in, const int* in_sizes, int n_in,
                              void* d_out, int out_size) {
    const float* vertices = (const float*)d_in[0];
    const int*   faces    = (const int*)d_in[1];
    const float* uv       = (const float*)d_in[2];
    const int*   uvfaces  = (const int*)d_in[3];
    const float* uvmap    = (const float*)d_in[4];

    int V = in_sizes[0] / 3;
    int K = in_sizes[1] / 3;
    int T = (int)(sqrt((double)(in_sizes[4] / 3)) + 0.5);
    int S = (int)(sqrt((double)(out_size / 4)) + 0.5);
    if (K > MAXK) K = MAXK;

    setup_kernel<<<1, 1024>>>(vertices, faces, V, K);

    dim3 blk(32, 8);
    dim3 grd((S + 31) / 32, (S + 7) / 8);
    render_kernel<<<grd, blk>>>(uvfaces, uv, uvmap, (float*)d_out, S, T);
}

// round 15
// speedup vs baseline: 1.1173x; 1.0065x over previous
#include <cuda_runtime.h>
#include <math.h>

// ----------------------------------------------------------------------------
// Software rasterizer matching the JAX reference.
// winner(pixel) = lexicographic argmax over covering triangles of (z, index),
// zbuf init = min vertex z. Deferred shading (one bilinear sample per pixel).
// Triangles bucket-sorted by zmax desc; per-slot term key = bucket upper edge
// (+1 bucket pad) -> non-increasing and >= all remaining zmax + ulp slack.
// Render: 32x8 tile, 1 pixel/thread, per-survivor termination; chunks
// compacted against the tile at load time (global->reg->test->smem).
// This round: software-pipelined survivor loop (prefetch next term key) and
// 3 barriers/chunk instead of 5.
// ----------------------------------------------------------------------------

#define MAXK  2048
#define CHUNK 256
#define NBUK  256

__device__ float4 g_tri[MAXK * 4];   // bucket-ordered triangle structs
__device__ int    g_ntri;            // number of active slots
__device__ float  g_zinit;           // min vertex z

__device__ __forceinline__ float blk_reduce(float v, bool do_min, float* s_red, int tid) {
    for (int o = 16; o > 0; o >>= 1) {
        float u = __shfl_xor_sync(0xffffffffu, v, o);
        v = do_min ? fminf(v, u) : fmaxf(v, u);
    }
    if ((tid & 31) == 0) s_red[tid >> 5] = v;
    __syncthreads();
    if (tid < 32) {
        float u = s_red[tid];
        for (int o = 16; o > 0; o >>= 1) {
            float w = __shfl_xor_sync(0xffffffffu, u, o);
            u = do_min ? fminf(u, w) : fmaxf(u, w);
        }
        if (tid == 0) s_red[0] = u;
    }
    __syncthreads();
    float r = s_red[0];
    __syncthreads();
    return r;
}

// ---- fused setup: zinit + zmax + bucket sort + struct build ----------------
__global__ void __launch_bounds__(1024) setup_kernel(
    const float* __restrict__ vertices, const int* __restrict__ faces,
    int V, int K)
{
    __shared__ float s_zmax[MAXK];
    __shared__ int   s_pos[MAXK];
    __shared__ int   s_hist[NBUK];
    __shared__ int   s_cnt[NBUK];
    __shared__ float s_red[32];
    __shared__ int   sh_n;
    int tid = threadIdx.x;

    // 1. zinit = min vertex z
    float m = INFINITY;
    for (int v = tid; v < V; v += 1024) m = fminf(m, vertices[v * 3 + 2]);
    m = blk_reduce(m, true, s_red, tid);
    if (tid == 0) g_zinit = m;

    // 2. per-triangle zmax (-inf if culled)
    float mymax = -INFINITY, mymin = INFINITY;
    for (int t = tid; t < K; t += 1024) {
        int i0 = faces[3*t], i1 = faces[3*t+1], i2 = faces[3*t+2];
        float v0x = vertices[i0*3+0], v0y = vertices[i0*3+1], v0z = vertices[i0*3+2];
        float v1x = vertices[i1*3+0], v1y = vertices[i1*3+1], v1z = vertices[i1*3+2];
        float v2x = vertices[i2*3+0], v2y = vertices[i2*3+1], v2z = vertices[i2*3+2];
        float w = (v1x - v0x) * (v2y - v0y) - (v1y - v0y) * (v2x - v0x);
        float zm = -INFINITY;
        if (w >= 1e-9f) {
            zm = fmaxf(v0z, fmaxf(v1z, v2z));
            mymax = fmaxf(mymax, zm);
            mymin = fminf(mymin, zm);
        }
        s_zmax[t] = zm;
    }
    float zh = blk_reduce(mymax, false, s_red, tid);
    float zl = blk_reduce(mymin, true,  s_red, tid);
    float wd = fmaxf((zh - zl) / (float)NBUK, 1e-30f);

    // 3. histogram (bucket 0 = highest zmax)
    if (tid < NBUK) s_hist[tid] = 0;
    __syncthreads();
    for (int t = tid; t < K; t += 1024) {
        float zm = s_zmax[t];
        if (zm != -INFINITY) {
            int b = (int)((zh - zm) / wd);
            b = min(max(b, 0), NBUK - 1);
            atomicAdd(&s_hist[b], 1);
        }
    }
    __syncthreads();

    // 4. exclusive scan (single warp: 8 buckets per lane + shfl scan)
    if (tid < 32) {
        int base2 = tid * 8;
        int v[8]; int s = 0;
        #pragma unroll
        for (int q = 0; q < 8; ++q) { v[q] = s_hist[base2 + q]; s += v[q]; }
        int incl = s;
        for (int o = 1; o < 32; o <<= 1) {
            int u = __shfl_up_sync(0xffffffffu, incl, o);
            if (tid >= o) incl += u;
        }
        int run = incl - s;
        #pragma unroll
        for (int q = 0; q < 8; ++q) { s_cnt[base2 + q] = run; run += v[q]; }
        if (tid == 31) sh_n = run;
    }
    __syncthreads();

    // 5. scatter slot assignment
    for (int t = tid; t < K; t += 1024) {
        float zm = s_zmax[t];
        int pos = -1;
        if (zm != -INFINITY) {
            int b = (int)((zh - zm) / wd);
            b = min(max(b, 0), NBUK - 1);
            pos = atomicAdd(&s_cnt[b], 1);
        }
        s_pos[t] = pos;
    }
    if (tid == 0) g_ntri = sh_n;
    __syncthreads();

    // 6. build structs. term key = bucket upper edge + one-bucket pad:
    //    term(b) = zh - (b-1)*wd >= zmax of everything in buckets >= b,
    //    margin ~wd >> f32 rounding; non-increasing across slots.
    // Layout per slot (4 x float4):
    //  [0] A0 B0 C0 term   (edge pAB: A*px + B*py + C)
    //  [1] A1 B1 C1 z0     (edge pCB -> w1)
    //  [2] A2 B2 C2 z1     (edge pCA -> w2)
    //  [3] w   z2  idx  0
    for (int t = tid; t < K; t += 1024) {
        int pos = s_pos[t];
        if (pos < 0) continue;
        float zm = s_zmax[t];
        int b = (int)((zh - zm) / wd);
        b = min(max(b, 0), NBUK - 1);
        float term = zh - (float)(b - 1) * wd;

        int i0 = faces[t*3+0], i1 = faces[t*3+1], i2 = faces[t*3+2];
        float v0x = vertices[i0*3+0], v0y = vertices[i0*3+1], v0z = vertices[i0*3+2];
        float v1x = vertices[i1*3+0], v1y = vertices[i1*3+1], v1z = vertices[i1*3+2];
        float v2x = vertices[i2*3+0], v2y = vertices[i2*3+1], v2z = vertices[i2*3+2];
        float w = (v1x - v0x) * (v2y - v0y) - (v1y - v0y) * (v2x - v0x);

        float a0 = v0y - v1y, b0 = v0x - v1x;
        float C0 = (float)((double)v1y * (double)b0 - (double)v1x * (double)a0);
        float a1 = v1y - v2y, b1 = v1x - v2x;
        float C1 = (float)((double)v2y * (double)b1 - (double)v2x * (double)a1);
        float a2 = v2y - v0y, b2 = v2x - v0x;
        float C2 = (float)((double)v0y * (double)b2 - (double)v0x * (double)a2);

        g_tri[pos*4+0] = make_float4(a0, -b0, C0, term);
        g_tri[pos*4+1] = make_float4(a1, -b1, C1, v0z);
        g_tri[pos*4+2] = make_float4(a2, -b2, C2, v1z);
        g_tri[pos*4+3] = make_float4(w, v2z, __int_as_float(t), 0.0f);
    }
}

// ---- main render: 32x8 tile, 1 pixel/thread --------------------------------
__global__ void __launch_bounds__(256) render_kernel(
    const int* __restrict__ uvfaces, const float* __restrict__ uv,
    const float* __restrict__ uvmap, float* __restrict__ out,
    int S, int T)
{
    __shared__ float4 s_ktri[CHUNK * 4];   // compacted survivors (dense)
    __shared__ int    s_wcnt[8];
    __shared__ float  s_head;              // chunk-head term key

    int n = g_ntri;

    int j = blockIdx.x * 32 + threadIdx.x;
    int i = blockIdx.y * 8 + threadIdx.y;
    int tid = threadIdx.y * 32 + threadIdx.x;
    int warp = tid >> 5, lane = tid & 31;
    bool inrange = (j < S) && (i < S);
    int jc = min(j, S - 1), ic = min(i, S - 1);

    // pts[i][j] = (lin[j], lin[S-1-i]), lin = linspace(-1, 1, S)
    float step = 2.0f / (float)(S - 1);
    float px = fmaf((float)jc, step, -1.0f);
    float py = fmaf((float)(S - 1 - ic), step, -1.0f);

    // tile bounds in (px, py) space
    int j0 = min(blockIdx.x * 32,      S - 1), j1 = min(blockIdx.x * 32 + 31, S - 1);
    int i0 = min(blockIdx.y * 8,       S - 1), i1 = min(blockIdx.y * 8 + 7,   S - 1);
    float xl = fmaf((float)j0, step, -1.0f), xh = fmaf((float)j1, step, -1.0f);
    float yl = fmaf((float)(S - 1 - i1), step, -1.0f);
    float yh = fmaf((float)(S - 1 - i0), step, -1.0f);

    float bestz = g_zinit;
    int   bestk = -1;
    float bw1 = 0.f, bw2 = 0.f;
    bool done = false;

    for (int base = 0; base < n; base += CHUNK) {
        int cnt = min(CHUNK, n - base);
        // NOTE: no top barrier needed — the __syncthreads_and at loop end
        // orders the previous iteration's s_ktri reads before this one's writes.

        // --- compact-on-load: global -> registers -> tile test -> smem ---
        bool keep = false;
        float4 r0v, r1v, r2v;
        if (tid < cnt) {
            const float4* gp = &g_tri[(base + tid) * 4];
            r0v = gp[0]; r1v = gp[1]; r2v = gp[2];
            if (tid == 0) s_head = r0v.w;
            float m0 = fmaxf(r0v.x*xl, r0v.x*xh) + fmaxf(r0v.y*yl, r0v.y*yh) + r0v.z;
            float m1 = fmaxf(r1v.x*xl, r1v.x*xh) + fmaxf(r1v.y*yl, r1v.y*yh) + r1v.z;
            float m2 = fmaxf(r2v.x*xl, r2v.x*xh) + fmaxf(r2v.y*yl, r2v.y*yh) + r2v.z;
            keep = (fminf(m0, fminf(m1, m2)) > -1e-3f);  // margin >> f32 slack
        }
        unsigned ball = __ballot_sync(0xffffffffu, keep);
        int pre = __popc(ball & ((1u << lane) - 1u));
        if (lane == 0) s_wcnt[warp] = __popc(ball);
        __syncthreads();                    // barrier 1: s_wcnt visible
        // every thread sums warp counts itself (no extra barrier for offsets)
        int off = 0, tot = 0;
        #pragma unroll
        for (int w2 = 0; w2 < 8; ++w2) {
            int c2 = s_wcnt[w2];
            tot += c2;
            if (w2 < warp) off += c2;
        }
        if (keep) {
            float4 r3v = g_tri[(base + tid) * 4 + 3];
            int pos = off + pre;
            s_ktri[pos*4+0] = r0v;
            s_ktri[pos*4+1] = r1v;
            s_ktri[pos*4+2] = r2v;
            s_ktri[pos*4+3] = r3v;
        }
        __syncthreads();                    // barrier 2: s_ktri ready
        int lcnt = tot;

        if (!done) {
            if (s_head < bestz) {
                done = true;   // chunk-head term can't beat bestz -> nothing later can
            } else if (lcnt > 0) {
                // software-pipelined survivor scan: next term key prefetched
                // during the current body so the break check never waits on LDS.
                float4 a = s_ktri[0];
                int mI = 0;
                while (true) {
                    if (a.w < bestz) { done = true; break; }  // term non-increasing
                    float4 b = s_ktri[mI*4+1];
                    float4 c = s_ktri[mI*4+2];
                    int nx = min(mI + 1, lcnt - 1);
                    float4 an = s_ktri[nx*4+0];               // prefetch next
                    float e0 = fmaf(a.x, px, fmaf(a.y, py, a.z));
                    float e1 = fmaf(b.x, px, fmaf(b.y, py, b.z));
                    float e2 = fmaf(c.x, px, fmaf(c.y, py, c.z));
                    if (fminf(e0, fminf(e1, e2)) > 0.f) {
                        float4 d = s_ktri[mI*4+3];
                        float w1 = e1 / d.x;          // pCB / w (exact like ref)
                        float w2 = e2 / d.x;          // pCA / w
                        float w3 = 1.0f - w1 - w2;
                        float z = w1 * b.w + w2 * c.w + w3 * d.y;
                        int k = __float_as_int(d.z);
                        if (z > bestz || (z == bestz && k > bestk)) {
                            bestz = z; bestk = k; bw1 = w1; bw2 = w2;
                        }
                    }
                    a = an;
                    if (++mI >= lcnt) break;
                }
            }
        }
        if (__syncthreads_and((int)done)) break;   // barrier 3 + collective exit
    }

    if (!inrange) return;
    int SS = S * S;
    int p = i * S + j;

    if (bestk >= 0) {
        int f0 = uvfaces[bestk*3+0], f1 = uvfaces[bestk*3+1], f2i = uvfaces[bestk*3+2];
        float u0x = uv[f0*2+0]  * 2.0f - 1.0f, u0y = uv[f0*2+1]  * 2.0f - 1.0f;
        float u1x = uv[f1*2+0]  * 2.0f - 1.0f, u1y = uv[f1*2+1]  * 2.0f - 1.0f;
        float u2x = uv[f2i*2+0] * 2.0f - 1.0f, u2y = uv[f2i*2+1] * 2.0f - 1.0f;
        float w3 = 1.0f - bw1 - bw2;
        float x = bw1 * u0x + bw2 * u1x + w3 * u2x;
        float y = bw1 * u0y + bw2 * u1y + w3 * u2y;

        float ix = (x + 1.0f) * (float)(T - 1) * 0.5f;
        float iy = (y + 1.0f) * (float)(T - 1) * 0.5f;
        float ix0f = floorf(ix), iy0f = floorf(iy);
        float wx1 = ix - ix0f, wx0 = 1.0f - wx1;
        float wy1 = iy - iy0f, wy0 = 1.0f - wy1;
        int ix0 = (int)ix0f, iy0 = (int)iy0f;
        int ix1 = ix0 + 1,   iy1 = iy0 + 1;

        float m00 = (ix0 >= 0 && ix0 <= T-1 && iy0 >= 0 && iy0 <= T-1) ? 1.f : 0.f;
        float m01 = (ix1 >= 0 && ix1 <= T-1 && iy0 >= 0 && iy0 <= T-1) ? 1.f : 0.f;
        float m10 = (ix0 >= 0 && ix0 <= T-1 && iy1 >= 0 && iy1 <= T-1) ? 1.f : 0.f;
        float m11 = (ix1 >= 0 && ix1 <= T-1 && iy1 >= 0 && iy1 <= T-1) ? 1.f : 0.f;
        int cx0 = min(max(ix0, 0), T-1), cx1 = min(max(ix1, 0), T-1);
        int cy0 = min(max(iy0, 0), T-1), cy1 = min(max(iy1, 0), T-1);
        float k00 = (wy0 * wx0) * m00, k01 = (wy0 * wx1) * m01;
        float k10 = (wy1 * wx0) * m10, k11 = (wy1 * wx1) * m11;

        #pragma unroll
        for (int ch = 0; ch < 3; ++ch) {
            const float* img = uvmap + ch * T * T;
            float v = img[cy0*T + cx0] * k00 + img[cy0*T + cx1] * k01
                    + img[cy1*T + cx0] * k10 + img[cy1*T + cx1] * k11;
            out[ch*SS + p] = v;
        }
        out[3*SS + p] = 1.0f;
    } else {
        out[0*SS + p] = 0.f; out[1*SS + p] = 0.f;
        out[2*SS + p] = 0.f; out[3*SS + p] = 0.f;
    }
}

// ---- launch ----------------------------------------------------------------
extern "C" void kernel_launch(void* const* d_in, const int* in_sizes, int n_in,
                              void* d_out, int out_size) {
    const float* vertices = (const float*)d_in[0];
    const int*   faces    = (const int*)d_in[1];
    const float* uv       = (const float*)d_in[2];
    const int*   uvfaces  = (const int*)d_in[3];
    const float* uvmap    = (const float*)d_in[4];

    int V = in_sizes[0] / 3;
    int K = in_sizes[1] / 3;
    int T = (int)(sqrt((double)(in_sizes[4] / 3)) + 0.5);
    int S = (int)(sqrt((double)(out_size / 4)) + 0.5);
    if (K > MAXK) K = MAXK;

    setup_kernel<<<1, 1024>>>(vertices, faces, V, K);

    dim3 blk(32, 8);
    dim3 grd((S + 31) / 32, (S + 7) / 8);
    render_kernel<<<grd, blk>>>(uvfaces, uv, uvmap, (float*)d_out, S, T);
}

// round 16
// speedup vs baseline: 1.1182x; 1.0008x over previous
#include <cuda_runtime.h>
#include <math.h>

// ----------------------------------------------------------------------------
// Software rasterizer matching the JAX reference.
// winner(pixel) = lexicographic argmax over covering triangles of (z, index),
// zbuf init = min vertex z. Deferred shading (one bilinear sample per pixel).
// Triangles bucket-sorted by zmax desc; per-slot term key = bucket upper edge
// (+1 bucket pad) -> non-increasing and >= all remaining zmax + ulp slack.
// Render: PERSISTENT blocks + atomic tile work-stealing (592 blocks, 1024
// tiles); per tile: 32x8 pixels, 1 pixel/thread, per-survivor termination;
// chunks compacted against the tile at load time (global->reg->test->smem).
// ----------------------------------------------------------------------------

#define MAXK  2048
#define CHUNK 256
#define NBUK  256

__device__ float4 g_tri[MAXK * 4];   // bucket-ordered triangle structs
__device__ int    g_ntri;            // number of active slots
__device__ float  g_zinit;           // min vertex z
__device__ int    g_tilectr;         // persistent-render work counter

__device__ __forceinline__ float blk_reduce(float v, bool do_min, float* s_red, int tid) {
    for (int o = 16; o > 0; o >>= 1) {
        float u = __shfl_xor_sync(0xffffffffu, v, o);
        v = do_min ? fminf(v, u) : fmaxf(v, u);
    }
    if ((tid & 31) == 0) s_red[tid >> 5] = v;
    __syncthreads();
    if (tid < 32) {
        float u = s_red[tid];
        for (int o = 16; o > 0; o >>= 1) {
            float w = __shfl_xor_sync(0xffffffffu, u, o);
            u = do_min ? fminf(u, w) : fmaxf(u, w);
        }
        if (tid == 0) s_red[0] = u;
    }
    __syncthreads();
    float r = s_red[0];
    __syncthreads();
    return r;
}

// ---- fused setup: zinit + zmax + bucket sort + struct build ----------------
__global__ void __launch_bounds__(1024) setup_kernel(
    const float* __restrict__ vertices, const int* __restrict__ faces,
    int V, int K)
{
    __shared__ float s_zmax[MAXK];
    __shared__ int   s_pos[MAXK];
    __shared__ int   s_hist[NBUK];
    __shared__ int   s_cnt[NBUK];
    __shared__ float s_red[32];
    __shared__ int   sh_n;
    int tid = threadIdx.x;

    if (tid == 0) g_tilectr = 0;     // reset persistent-render work counter

    // 1. zinit = min vertex z
    float m = INFINITY;
    for (int v = tid; v < V; v += 1024) m = fminf(m, vertices[v * 3 + 2]);
    m = blk_reduce(m, true, s_red, tid);
    if (tid == 0) g_zinit = m;

    // 2. per-triangle zmax (-inf if culled)
    float mymax = -INFINITY, mymin = INFINITY;
    for (int t = tid; t < K; t += 1024) {
        int i0 = faces[3*t], i1 = faces[3*t+1], i2 = faces[3*t+2];
        float v0x = vertices[i0*3+0], v0y = vertices[i0*3+1], v0z = vertices[i0*3+2];
        float v1x = vertices[i1*3+0], v1y = vertices[i1*3+1], v1z = vertices[i1*3+2];
        float v2x = vertices[i2*3+0], v2y = vertices[i2*3+1], v2z = vertices[i2*3+2];
        float w = (v1x - v0x) * (v2y - v0y) - (v1y - v0y) * (v2x - v0x);
        float zm = -INFINITY;
        if (w >= 1e-9f) {
            zm = fmaxf(v0z, fmaxf(v1z, v2z));
            mymax = fmaxf(mymax, zm);
            mymin = fminf(mymin, zm);
        }
        s_zmax[t] = zm;
    }
    float zh = blk_reduce(mymax, false, s_red, tid);
    float zl = blk_reduce(mymin, true,  s_red, tid);
    float wd = fmaxf((zh - zl) / (float)NBUK, 1e-30f);

    // 3. histogram (bucket 0 = highest zmax)
    if (tid < NBUK) s_hist[tid] = 0;
    __syncthreads();
    for (int t = tid; t < K; t += 1024) {
        float zm = s_zmax[t];
        if (zm != -INFINITY) {
            int b = (int)((zh - zm) / wd);
            b = min(max(b, 0), NBUK - 1);
            atomicAdd(&s_hist[b], 1);
        }
    }
    __syncthreads();

    // 4. exclusive scan (single warp: 8 buckets per lane + shfl scan)
    if (tid < 32) {
        int base2 = tid * 8;
        int v[8]; int s = 0;
        #pragma unroll
        for (int q = 0; q < 8; ++q) { v[q] = s_hist[base2 + q]; s += v[q]; }
        int incl = s;
        for (int o = 1; o < 32; o <<= 1) {
            int u = __shfl_up_sync(0xffffffffu, incl, o);
            if (tid >= o) incl += u;
        }
        int run = incl - s;
        #pragma unroll
        for (int q = 0; q < 8; ++q) { s_cnt[base2 + q] = run; run += v[q]; }
        if (tid == 31) sh_n = run;
    }
    __syncthreads();

    // 5. scatter slot assignment
    for (int t = tid; t < K; t += 1024) {
        float zm = s_zmax[t];
        int pos = -1;
        if (zm != -INFINITY) {
            int b = (int)((zh - zm) / wd);
            b = min(max(b, 0), NBUK - 1);
            pos = atomicAdd(&s_cnt[b], 1);
        }
        s_pos[t] = pos;
    }
    if (tid == 0) g_ntri = sh_n;
    __syncthreads();

    // 6. build structs. term key = bucket upper edge + one-bucket pad:
    //    term(b) = zh - (b-1)*wd >= zmax of everything in buckets >= b,
    //    margin ~wd >> f32 rounding; non-increasing across slots.
    // Layout per slot (4 x float4):
    //  [0] A0 B0 C0 term   (edge pAB: A*px + B*py + C)
    //  [1] A1 B1 C1 z0     (edge pCB -> w1)
    //  [2] A2 B2 C2 z1     (edge pCA -> w2)
    //  [3] w   z2  idx  0
    for (int t = tid; t < K; t += 1024) {
        int pos = s_pos[t];
        if (pos < 0) continue;
        float zm = s_zmax[t];
        int b = (int)((zh - zm) / wd);
        b = min(max(b, 0), NBUK - 1);
        float term = zh - (float)(b - 1) * wd;

        int i0 = faces[t*3+0], i1 = faces[t*3+1], i2 = faces[t*3+2];
        float v0x = vertices[i0*3+0], v0y = vertices[i0*3+1], v0z = vertices[i0*3+2];
        float v1x = vertices[i1*3+0], v1y = vertices[i1*3+1], v1z = vertices[i1*3+2];
        float v2x = vertices[i2*3+0], v2y = vertices[i2*3+1], v2z = vertices[i2*3+2];
        float w = (v1x - v0x) * (v2y - v0y) - (v1y - v0y) * (v2x - v0x);

        float a0 = v0y - v1y, b0 = v0x - v1x;
        float C0 = (float)((double)v1y * (double)b0 - (double)v1x * (double)a0);
        float a1 = v1y - v2y, b1 = v1x - v2x;
        float C1 = (float)((double)v2y * (double)b1 - (double)v2x * (double)a1);
        float a2 = v2y - v0y, b2 = v2x - v0x;
        float C2 = (float)((double)v0y * (double)b2 - (double)v0x * (double)a2);

        g_tri[pos*4+0] = make_float4(a0, -b0, C0, term);
        g_tri[pos*4+1] = make_float4(a1, -b1, C1, v0z);
        g_tri[pos*4+2] = make_float4(a2, -b2, C2, v1z);
        g_tri[pos*4+3] = make_float4(w, v2z, __int_as_float(t), 0.0f);
    }
}

// ---- main render: persistent blocks, 32x8 tile per work item ---------------
__global__ void __launch_bounds__(256) render_kernel(
    const int* __restrict__ uvfaces, const float* __restrict__ uv,
    const float* __restrict__ uvmap, float* __restrict__ out,
    int S, int T)
{
    __shared__ float4 s_ktri[CHUNK * 4];   // compacted survivors (dense)
    __shared__ int    s_wcnt[8];
    __shared__ float  s_head;              // chunk-head term key
    __shared__ int    s_tile;

    int n = g_ntri;
    float zinit = g_zinit;

    int tid = threadIdx.y * 32 + threadIdx.x;
    int warp = tid >> 5, lane = tid & 31;
    int tilesx = (S + 31) / 32;
    int tilesy = (S + 7) / 8;
    int numtiles = tilesx * tilesy;

    float step = 2.0f / (float)(S - 1);
    int SS = S * S;

    while (true) {
        if (tid == 0) s_tile = atomicAdd(&g_tilectr, 1);
        __syncthreads();
        int tile = s_tile;
        if (tile >= numtiles) break;          // uniform exit

        int bx = tile % tilesx, by = tile / tilesx;
        int j = bx * 32 + threadIdx.x;
        int i = by * 8 + threadIdx.y;
        bool inrange = (j < S) && (i < S);
        int jc = min(j, S - 1), ic = min(i, S - 1);

        // pts[i][j] = (lin[j], lin[S-1-i]), lin = linspace(-1, 1, S)
        float px = fmaf((float)jc, step, -1.0f);
        float py = fmaf((float)(S - 1 - ic), step, -1.0f);

        // tile bounds in (px, py) space
        int j0 = min(bx * 32,     S - 1), j1 = min(bx * 32 + 31, S - 1);
        int i0 = min(by * 8,      S - 1), i1 = min(by * 8 + 7,   S - 1);
        float xl = fmaf((float)j0, step, -1.0f), xh = fmaf((float)j1, step, -1.0f);
        float yl = fmaf((float)(S - 1 - i1), step, -1.0f);
        float yh = fmaf((float)(S - 1 - i0), step, -1.0f);

        float bestz = zinit;
        int   bestk = -1;
        float bw1 = 0.f, bw2 = 0.f;
        bool done = false;

        for (int base = 0; base < n; base += CHUNK) {
            int cnt = min(CHUNK, n - base);

            // --- compact-on-load: global -> registers -> tile test -> smem ---
            bool keep = false;
            float4 r0v, r1v, r2v;
            if (tid < cnt) {
                const float4* gp = &g_tri[(base + tid) * 4];
                r0v = gp[0]; r1v = gp[1]; r2v = gp[2];
                if (tid == 0) s_head = r0v.w;
                float m0 = fmaxf(r0v.x*xl, r0v.x*xh) + fmaxf(r0v.y*yl, r0v.y*yh) + r0v.z;
                float m1 = fmaxf(r1v.x*xl, r1v.x*xh) + fmaxf(r1v.y*yl, r1v.y*yh) + r1v.z;
                float m2 = fmaxf(r2v.x*xl, r2v.x*xh) + fmaxf(r2v.y*yl, r2v.y*yh) + r2v.z;
                keep = (fminf(m0, fminf(m1, m2)) > -1e-3f);  // margin >> f32 slack
            }
            unsigned ball = __ballot_sync(0xffffffffu, keep);
            int pre = __popc(ball & ((1u << lane) - 1u));
            if (lane == 0) s_wcnt[warp] = __popc(ball);
            __syncthreads();                    // s_wcnt (and prior s_ktri reads) settled
            int off = 0, tot = 0;
            #pragma unroll
            for (int w2 = 0; w2 < 8; ++w2) {
                int c2 = s_wcnt[w2];
                tot += c2;
                if (w2 < warp) off += c2;
            }
            if (keep) {
                float4 r3v = g_tri[(base + tid) * 4 + 3];
                int pos = off + pre;
                s_ktri[pos*4+0] = r0v;
                s_ktri[pos*4+1] = r1v;
                s_ktri[pos*4+2] = r2v;
                s_ktri[pos*4+3] = r3v;
            }
            __syncthreads();                    // s_ktri ready
            int lcnt = tot;

            if (!done) {
                if (s_head < bestz) {
                    done = true;   // chunk-head term can't beat bestz
                } else {
                    for (int mI = 0; mI < lcnt; ++mI) {
                        float4 a = s_ktri[mI*4+0];
                        if (a.w < bestz) { done = true; break; }  // term non-increasing
                        float e0 = fmaf(a.x, px, fmaf(a.y, py, a.z));
                        float4 b = s_ktri[mI*4+1];
                        float e1 = fmaf(b.x, px, fmaf(b.y, py, b.z));
                        float4 c = s_ktri[mI*4+2];
                        float e2 = fmaf(c.x, px, fmaf(c.y, py, c.z));
                        if (fminf(e0, fminf(e1, e2)) > 0.f) {
                            float4 d = s_ktri[mI*4+3];
                            float w1 = e1 / d.x;          // pCB / w (exact like ref)
                            float w2 = e2 / d.x;          // pCA / w
                            float w3 = 1.0f - w1 - w2;
                            float z = w1 * b.w + w2 * c.w + w3 * d.y;
                            int k = __float_as_int(d.z);
                            if (z > bestz || (z == bestz && k > bestk)) {
                                bestz = z; bestk = k; bw1 = w1; bw2 = w2;
                            }
                        }
                    }
                }
            }
            if (__syncthreads_and((int)done)) break;   // collective exit
        }

        // deferred shading for this tile
        if (inrange) {
            int p = i * S + j;
            if (bestk >= 0) {
                int f0 = uvfaces[bestk*3+0], f1 = uvfaces[bestk*3+1], f2i = uvfaces[bestk*3+2];
                float u0x = uv[f0*2+0]  * 2.0f - 1.0f, u0y = uv[f0*2+1]  * 2.0f - 1.0f;
                float u1x = uv[f1*2+0]  * 2.0f - 1.0f, u1y = uv[f1*2+1]  * 2.0f - 1.0f;
                float u2x = uv[f2i*2+0] * 2.0f - 1.0f, u2y = uv[f2i*2+1] * 2.0f - 1.0f;
                float w3 = 1.0f - bw1 - bw2;
                float x = bw1 * u0x + bw2 * u1x + w3 * u2x;
                float y = bw1 * u0y + bw2 * u1y + w3 * u2y;

                float ix = (x + 1.0f) * (float)(T - 1) * 0.5f;
                float iy = (y + 1.0f) * (float)(T - 1) * 0.5f;
                float ix0f = floorf(ix), iy0f = floorf(iy);
                float wx1 = ix - ix0f, wx0 = 1.0f - wx1;
                float wy1 = iy - iy0f, wy0 = 1.0f - wy1;
                int ix0 = (int)ix0f, iy0 = (int)iy0f;
                int ix1 = ix0 + 1,   iy1 = iy0 + 1;

                float m00 = (ix0 >= 0 && ix0 <= T-1 && iy0 >= 0 && iy0 <= T-1) ? 1.f : 0.f;
                float m01 = (ix1 >= 0 && ix1 <= T-1 && iy0 >= 0 && iy0 <= T-1) ? 1.f : 0.f;
                float m10 = (ix0 >= 0 && ix0 <= T-1 && iy1 >= 0 && iy1 <= T-1) ? 1.f : 0.f;
                float m11 = (ix1 >= 0 && ix1 <= T-1 && iy1 >= 0 && iy1 <= T-1) ? 1.f : 0.f;
                int cx0 = min(max(ix0, 0), T-1), cx1 = min(max(ix1, 0), T-1);
                int cy0 = min(max(iy0, 0), T-1), cy1 = min(max(iy1, 0), T-1);
                float k00 = (wy0 * wx0) * m00, k01 = (wy0 * wx1) * m01;
                float k10 = (wy1 * wx0) * m10, k11 = (wy1 * wx1) * m11;

                #pragma unroll
                for (int ch = 0; ch < 3; ++ch) {
                    const float* img = uvmap + ch * T * T;
                    float v = img[cy0*T + cx0] * k00 + img[cy0*T + cx1] * k01
                            + img[cy1*T + cx0] * k10 + img[cy1*T + cx1] * k11;
                    out[ch*SS + p] = v;
                }
                out[3*SS + p] = 1.0f;
            } else {
                out[0*SS + p] = 0.f; out[1*SS + p] = 0.f;
                out[2*SS + p] = 0.f; out[3*SS + p] = 0.f;
            }
        }
        __syncthreads();   // all threads done with s_tile/s_ktri before next grab
    }
}

// ---- launch ----------------------------------------------------------------
extern "C" void kernel_launch(void* const* d_in, const int* in_sizes, int n_in,
                              void* d_out, int out_size) {
    const float* vertices = (const float*)d_in[0];
    const int*   faces    = (const int*)d_in[1];
    const float* uv       = (const float*)d_in[2];
    const int*   uvfaces  = (const int*)d_in[3];
    const float* uvmap    = (const float*)d_in[4];

    int V = in_sizes[0] / 3;
    int K = in_sizes[1] / 3;
    int T = (int)(sqrt((double)(in_sizes[4] / 3)) + 0.5);
    int S = (int)(sqrt((double)(out_size / 4)) + 0.5);
    if (K > MAXK) K = MAXK;

    setup_kernel<<<1, 1024>>>(vertices, faces, V, K);

    dim3 blk(32, 8);
    render_kernel<<<592, blk>>>(uvfaces, uv, uvmap, (float*)d_out, S, T);
}